// round 1
// baseline (speedup 1.0000x reference)
#include <cuda_runtime.h>

#define W_IMG 3840
#define H_IMG 2160
#define TILE 32
#define HALO 34   // TILE + 2 (pool halo)
#define DEP  35   // TILE + 3 (depth needs +1 right/down beyond halo)
#define SSTR 36   // padded shared stride
#define NTHREADS 256

__device__ double g_num;
__device__ unsigned int g_cnt;

__global__ void zero_kernel() { g_num = 0.0; g_cnt = 0u; }

__global__ void finalize_kernel(float* out) {
    out[0] = (float)(g_num / ((double)g_cnt * 3.0));
}

__launch_bounds__(NTHREADS)
__global__ void shading_loss_kernel(const float* __restrict__ depth,
                                    const float* __restrict__ rgb,
                                    const int*   __restrict__ mask,
                                    const float* __restrict__ l,
                                    const float* __restrict__ Kc)
{
    __shared__ float s_depth[DEP * SSTR];
    __shared__ float s_ren[3][HALO * SSTR];
    __shared__ float s_rgb[3][HALO * SSTR];
    __shared__ unsigned char s_mask[HALO * SSTR];
    __shared__ float s_Ki[9];
    __shared__ float s_l[27];
    __shared__ float s_red[8];
    __shared__ unsigned int s_redc[8];

    const int tid  = threadIdx.x;
    const int col0 = blockIdx.x * TILE;
    const int row0 = blockIdx.y * TILE;

    // 3x3 inverse of camera matrix (adjugate), once per block
    if (tid == 0) {
        float a = Kc[0], b = Kc[1], c = Kc[2];
        float d = Kc[3], e = Kc[4], f = Kc[5];
        float g = Kc[6], h = Kc[7], i = Kc[8];
        float A =  (e*i - f*h), B = -(d*i - f*g), C =  (d*h - e*g);
        float det = a*A + b*B + c*C;
        float inv = 1.0f / det;
        s_Ki[0] = A * inv;             s_Ki[1] = -(b*i - c*h) * inv;  s_Ki[2] =  (b*f - c*e) * inv;
        s_Ki[3] = B * inv;             s_Ki[4] =  (a*i - c*g) * inv;  s_Ki[5] = -(a*f - c*d) * inv;
        s_Ki[6] = C * inv;             s_Ki[7] = -(a*h - b*g) * inv;  s_Ki[8] =  (a*e - b*d) * inv;
    }
    if (tid < 27) s_l[tid] = l[tid];

    // ---- cooperative loads (zero outside the image) ----
    for (int idx = tid; idx < DEP * DEP; idx += NTHREADS) {
        int r = idx / DEP, c = idx % DEP;
        int gr = row0 - 1 + r, gc = col0 - 1 + c;
        float v = 0.0f;
        if (gr >= 0 && gr < H_IMG && gc >= 0 && gc < W_IMG)
            v = depth[gr * W_IMG + gc];
        s_depth[r * SSTR + c] = v;
    }
    for (int idx = tid; idx < HALO * HALO; idx += NTHREADS) {
        int r = idx / HALO, c = idx % HALO;
        int gr = row0 - 1 + r, gc = col0 - 1 + c;
        int m = 0;
        if (gr >= 0 && gr < H_IMG && gc >= 0 && gc < W_IMG)
            m = mask[gr * W_IMG + gc] > 0;
        s_mask[r * SSTR + c] = (unsigned char)m;
    }
    for (int idx = tid; idx < HALO * HALO * 3; idx += NTHREADS) {
        int r = idx / (HALO * 3), e = idx % (HALO * 3);
        int cc = e / 3, ch = e % 3;
        int gr = row0 - 1 + r, gc = col0 - 1 + cc;
        float v = 0.0f;
        if (gr >= 0 && gr < H_IMG && gc >= 0 && gc < W_IMG)
            v = rgb[(gr * W_IMG + gc) * 3 + ch];
        s_rgb[ch][r * SSTR + cc] = v;
    }
    __syncthreads();

    // ---- phase 1: masked render over the 34x34 halo region ----
    for (int idx = tid; idx < HALO * HALO; idx += NTHREADS) {
        int r = idx / HALO, c = idx % HALO;
        int gr = row0 - 1 + r, gc = col0 - 1 + c;
        float b0 = 0.0f, b1 = 0.0f, b2 = 0.0f;
        bool valid = (gr >= 0) && (gr < H_IMG) && (gc >= 0) && (gc < W_IMG)
                     && (s_mask[r * SSTR + c] != 0);
        if (valid) {
            float x = (float)gc, y = (float)gr;
            float rx = s_Ki[0] * x + s_Ki[1] * y + s_Ki[2];
            float ry = s_Ki[3] * x + s_Ki[4] * y + s_Ki[5];
            float rz = s_Ki[6] * x + s_Ki[7] * y + s_Ki[8];
            float d0 = s_depth[r * SSTR + c];
            float dl = s_depth[r * SSTR + c + 1];        // right neighbor (0 if OOB)
            float du = s_depth[(r + 1) * SSTR + c];      // down  neighbor (0 if OOB)
            float px = rx * d0, py = ry * d0, pz = rz * d0;
            float plx = (rx + s_Ki[0]) * dl, ply = (ry + s_Ki[3]) * dl, plz = (rz + s_Ki[6]) * dl;
            float pux = (rx + s_Ki[1]) * du, puy = (ry + s_Ki[4]) * du, puz = (rz + s_Ki[7]) * du;
            float ax = plx - px, ay = ply - py, az = plz - pz;
            float bx = pux - px, by = puy - py, bz = puz - pz;
            float nx = ay * bz - az * by;
            float ny = az * bx - ax * bz;
            float nz = ax * by - ay * bx;
            float nn = nx * nx + ny * ny + nz * nz;
            float invn = 1.0f / fmaxf(sqrtf(nn), 1e-12f);
            nx *= invn; ny *= invn; nz *= invn;
            float Hs[9];
            Hs[0] = 1.0f;       Hs[1] = ny;          Hs[2] = nz;
            Hs[3] = nx;         Hs[4] = nx * ny;     Hs[5] = ny * nz;
            Hs[6] = -nx * nx - ny * ny + 2.0f * nz * nz;
            Hs[7] = nz * nx;    Hs[8] = nx * nx - ny * ny;
            #pragma unroll
            for (int k = 0; k < 9; k++) {
                b0 += Hs[k] * s_l[k * 3 + 0];
                b1 += Hs[k] * s_l[k * 3 + 1];
                b2 += Hs[k] * s_l[k * 3 + 2];
            }
        }
        s_ren[0][r * SSTR + c] = b0;
        s_ren[1][r * SSTR + c] = b1;
        s_ren[2][r * SSTR + c] = b2;
    }
    __syncthreads();

    // ---- phase 2: 3x3 avgpool (sliding vertical window) + masked MSE ----
    const int c  = tid & 31;        // center column within tile
    const int rg = tid >> 5;        // row group 0..7, each owns 4 rows
    const int hc  = c + 1;          // halo coords
    const int hr0 = rg * 4 + 1;
    const float inv9 = 1.0f / 9.0f;

    float acc = 0.0f;
    unsigned int cnt = 0;

    float rp[3], rcu[3], gp[3], gcu[3];
    #pragma unroll
    for (int ch = 0; ch < 3; ch++) {
        int o = (hr0 - 1) * SSTR + hc;
        rp[ch]  = s_ren[ch][o - 1] + s_ren[ch][o] + s_ren[ch][o + 1];
        gp[ch]  = s_rgb[ch][o - 1] + s_rgb[ch][o] + s_rgb[ch][o + 1];
        o += SSTR;
        rcu[ch] = s_ren[ch][o - 1] + s_ren[ch][o] + s_ren[ch][o + 1];
        gcu[ch] = s_rgb[ch][o - 1] + s_rgb[ch][o] + s_rgb[ch][o + 1];
    }
    #pragma unroll
    for (int k = 0; k < 4; k++) {
        int hr = hr0 + k;
        int on = (hr + 1) * SSTR + hc;
        int oc = hr * SSTR + hc;
        unsigned char m = s_mask[oc];
        #pragma unroll
        for (int ch = 0; ch < 3; ch++) {
            float rn = s_ren[ch][on - 1] + s_ren[ch][on] + s_ren[ch][on + 1];
            float gn = s_rgb[ch][on - 1] + s_rgb[ch][on] + s_rgb[ch][on + 1];
            if (m) {
                float rmean = (rp[ch] + rcu[ch] + rn) * inv9;
                float gmean = (gp[ch] + gcu[ch] + gn) * inv9;
                float diff = (s_ren[ch][oc] - rmean) - (s_rgb[ch][oc] - gmean);
                acc += diff * diff;
            }
            rp[ch] = rcu[ch]; rcu[ch] = rn;
            gp[ch] = gcu[ch]; gcu[ch] = gn;
        }
        cnt += (unsigned int)m;
    }

    // ---- block reduction ----
    #pragma unroll
    for (int off = 16; off > 0; off >>= 1) {
        acc += __shfl_down_sync(0xffffffffu, acc, off);
        cnt += __shfl_down_sync(0xffffffffu, cnt, off);
    }
    int lane = tid & 31, warp = tid >> 5;
    if (lane == 0) { s_red[warp] = acc; s_redc[warp] = cnt; }
    __syncthreads();
    if (warp == 0) {
        float a = (lane < 8) ? s_red[lane] : 0.0f;
        unsigned int cn = (lane < 8) ? s_redc[lane] : 0u;
        #pragma unroll
        for (int off = 4; off > 0; off >>= 1) {
            a  += __shfl_down_sync(0xffffffffu, a, off);
            cn += __shfl_down_sync(0xffffffffu, cn, off);
        }
        if (lane == 0) {
            atomicAdd(&g_num, (double)a);
            atomicAdd(&g_cnt, cn);
        }
    }
}

extern "C" void kernel_launch(void* const* d_in, const int* in_sizes, int n_in,
                              void* d_out, int out_size) {
    const float* depth = (const float*)d_in[0];
    const float* rgb   = (const float*)d_in[1];
    const int*   mask  = (const int*)d_in[2];
    const float* l     = (const float*)d_in[3];
    const float* Kc    = (const float*)d_in[4];

    zero_kernel<<<1, 1>>>();
    dim3 grid((W_IMG + TILE - 1) / TILE, (H_IMG + TILE - 1) / TILE);
    shading_loss_kernel<<<grid, NTHREADS>>>(depth, rgb, mask, l, Kc);
    finalize_kernel<<<1, 1>>>((float*)d_out);
}

// round 2
// speedup vs baseline: 1.4946x; 1.4946x over previous
#include <cuda_runtime.h>

#define W_IMG 3840
#define H_IMG 2160
#define TILE 32
#define HALO 34   // TILE + 2 (pool halo)
#define DEP  35   // TILE + 3 (depth needs +1 right/down beyond halo)
#define SSTR 36   // padded shared stride
#define NTHREADS 256
#define GRID_X ((W_IMG + TILE - 1) / TILE)   // 120
#define GRID_Y ((H_IMG + TILE - 1) / TILE)   // 68
#define NBLOCKS (GRID_X * GRID_Y)

__device__ double g_num;
__device__ unsigned int g_cnt;
__device__ unsigned int g_ticket;

// Compute q = (mask ? B(normal) - rgb : -rgb) for one halo pixel.
__device__ __forceinline__ void shade_q(
    float x, float y, float d0, float dl, float du, int m,
    float rg0, float rg1, float rg2,
    const float* __restrict__ Ki, const float* __restrict__ L,
    float& q0, float& q1, float& q2)
{
    float b0 = 0.0f, b1 = 0.0f, b2 = 0.0f;
    if (m) {
        float rx = Ki[0] * x + Ki[1] * y + Ki[2];
        float ry = Ki[3] * x + Ki[4] * y + Ki[5];
        float rz = Ki[6] * x + Ki[7] * y + Ki[8];
        float px = rx * d0, py = ry * d0, pz = rz * d0;
        float plx = (rx + Ki[0]) * dl, ply = (ry + Ki[3]) * dl, plz = (rz + Ki[6]) * dl;
        float pux = (rx + Ki[1]) * du, puy = (ry + Ki[4]) * du, puz = (rz + Ki[7]) * du;
        float ax = plx - px, ay = ply - py, az = plz - pz;
        float bx = pux - px, by = puy - py, bz = puz - pz;
        float nx = ay * bz - az * by;
        float ny = az * bx - ax * bz;
        float nz = ax * by - ay * bx;
        float nn = nx * nx + ny * ny + nz * nz;
        float invn = rsqrtf(fmaxf(nn, 1e-24f));
        nx *= invn; ny *= invn; nz *= invn;
        float nx2 = nx * nx, ny2 = ny * ny, nz2 = nz * nz;
        float Hs1 = ny, Hs2 = nz, Hs3 = nx;
        float Hs4 = nx * ny, Hs5 = ny * nz;
        float Hs6 = -nx2 - ny2 + 2.0f * nz2;
        float Hs7 = nz * nx, Hs8 = nx2 - ny2;
        b0 = L[0] + Hs1*L[3]  + Hs2*L[6]  + Hs3*L[9]  + Hs4*L[12] + Hs5*L[15] + Hs6*L[18] + Hs7*L[21] + Hs8*L[24];
        b1 = L[1] + Hs1*L[4]  + Hs2*L[7]  + Hs3*L[10] + Hs4*L[13] + Hs5*L[16] + Hs6*L[19] + Hs7*L[22] + Hs8*L[25];
        b2 = L[2] + Hs1*L[5]  + Hs2*L[8]  + Hs3*L[11] + Hs4*L[14] + Hs5*L[17] + Hs6*L[20] + Hs7*L[23] + Hs8*L[26];
    }
    q0 = b0 - rg0;
    q1 = b1 - rg1;
    q2 = b2 - rg2;
}

__launch_bounds__(NTHREADS)
__global__ void shading_loss_kernel(const float* __restrict__ depth,
                                    const float* __restrict__ rgb,
                                    const int*   __restrict__ mask,
                                    const float* __restrict__ l,
                                    const float* __restrict__ Kc,
                                    float* __restrict__ out)
{
    __shared__ float s_depth[DEP * SSTR];
    __shared__ float s_q[3][HALO * SSTR];
    __shared__ unsigned char s_mask[HALO * SSTR];
    __shared__ float s_Ki[9];
    __shared__ float s_l[27];
    __shared__ float s_red[8];
    __shared__ unsigned int s_redc[8];

    const int tid  = threadIdx.x;
    const int col0 = blockIdx.x * TILE;
    const int row0 = blockIdx.y * TILE;

    const bool interior = (col0 >= 1) && (row0 >= 1) &&
                          (col0 + HALO <= W_IMG) && (row0 + HALO <= H_IMG);

    // camera inverse (adjugate), 27 light coeffs
    if (tid == 0) {
        float a = Kc[0], b = Kc[1], c = Kc[2];
        float d = Kc[3], e = Kc[4], f = Kc[5];
        float g = Kc[6], h = Kc[7], i = Kc[8];
        float A =  (e*i - f*h), B = -(d*i - f*g), C =  (d*h - e*g);
        float inv = 1.0f / (a*A + b*B + c*C);
        s_Ki[0] = A * inv;            s_Ki[1] = -(b*i - c*h) * inv;  s_Ki[2] =  (b*f - c*e) * inv;
        s_Ki[3] = B * inv;            s_Ki[4] =  (a*i - c*g) * inv;  s_Ki[5] = -(a*f - c*d) * inv;
        s_Ki[6] = C * inv;            s_Ki[7] = -(a*h - b*g) * inv;  s_Ki[8] =  (a*e - b*d) * inv;
    }
    if (tid < 27) s_l[tid] = l[tid];

    // ---- stage 1: depth halo ----
    const long base0 = (long)(row0 - 1) * W_IMG + (col0 - 1);
    if (interior) {
        #pragma unroll 2
        for (int idx = tid; idx < DEP * DEP; idx += NTHREADS) {
            int r = idx / DEP, c = idx % DEP;
            s_depth[r * SSTR + c] = depth[base0 + r * W_IMG + c];
        }
    } else {
        for (int idx = tid; idx < DEP * DEP; idx += NTHREADS) {
            int r = idx / DEP, c = idx % DEP;
            int gr = row0 - 1 + r, gc = col0 - 1 + c;
            float v = 0.0f;
            if (gr >= 0 && gr < H_IMG && gc >= 0 && gc < W_IMG)
                v = depth[(long)gr * W_IMG + gc];
            s_depth[r * SSTR + c] = v;
        }
    }
    __syncthreads();

    // ---- stage 2: shade -> q over 34x34 halo (rgb + mask straight from gmem) ----
    if (interior) {
        #pragma unroll 2
        for (int idx = tid; idx < HALO * HALO; idx += NTHREADS) {
            int r = idx / HALO, c = idx % HALO;
            long goff = base0 + r * W_IMG + c;
            int m = mask[goff] > 0;
            float rg0 = rgb[goff * 3 + 0];
            float rg1 = rgb[goff * 3 + 1];
            float rg2 = rgb[goff * 3 + 2];
            float d0 = s_depth[r * SSTR + c];
            float dl = s_depth[r * SSTR + c + 1];
            float du = s_depth[(r + 1) * SSTR + c];
            float q0, q1, q2;
            shade_q((float)(col0 - 1 + c), (float)(row0 - 1 + r),
                    d0, dl, du, m, rg0, rg1, rg2, s_Ki, s_l, q0, q1, q2);
            s_q[0][r * SSTR + c] = q0;
            s_q[1][r * SSTR + c] = q1;
            s_q[2][r * SSTR + c] = q2;
            s_mask[r * SSTR + c] = (unsigned char)m;
        }
    } else {
        for (int idx = tid; idx < HALO * HALO; idx += NTHREADS) {
            int r = idx / HALO, c = idx % HALO;
            int gr = row0 - 1 + r, gc = col0 - 1 + c;
            bool inimg = (gr >= 0 && gr < H_IMG && gc >= 0 && gc < W_IMG);
            int m = 0;
            float rg0 = 0.0f, rg1 = 0.0f, rg2 = 0.0f;
            if (inimg) {
                long goff = (long)gr * W_IMG + gc;
                m = mask[goff] > 0;
                rg0 = rgb[goff * 3 + 0];
                rg1 = rgb[goff * 3 + 1];
                rg2 = rgb[goff * 3 + 2];
            }
            float d0 = s_depth[r * SSTR + c];
            float dl = s_depth[r * SSTR + c + 1];
            float du = s_depth[(r + 1) * SSTR + c];
            float q0, q1, q2;
            shade_q((float)gc, (float)gr, d0, dl, du, m, rg0, rg1, rg2,
                    s_Ki, s_l, q0, q1, q2);
            s_q[0][r * SSTR + c] = q0;
            s_q[1][r * SSTR + c] = q1;
            s_q[2][r * SSTR + c] = q2;
            s_mask[r * SSTR + c] = (unsigned char)m;
        }
    }
    __syncthreads();

    // ---- stage 3: 3x3 avgpool of q (vertical sliding window) + masked MSE ----
    const int c  = tid & 31;
    const int rg = tid >> 5;           // each thread: 4 output rows
    const int hc  = c + 1;
    const int hr0 = rg * 4 + 1;
    const float inv9 = 1.0f / 9.0f;

    float acc = 0.0f;
    unsigned int cnt = 0;

    float sp[3], sc[3];
    #pragma unroll
    for (int ch = 0; ch < 3; ch++) {
        int o = (hr0 - 1) * SSTR + hc;
        sp[ch] = s_q[ch][o - 1] + s_q[ch][o] + s_q[ch][o + 1];
        o += SSTR;
        sc[ch] = s_q[ch][o - 1] + s_q[ch][o] + s_q[ch][o + 1];
    }
    #pragma unroll
    for (int k = 0; k < 4; k++) {
        int hr = hr0 + k;
        int on = (hr + 1) * SSTR + hc;
        int oc = hr * SSTR + hc;
        unsigned char m = s_mask[oc];
        #pragma unroll
        for (int ch = 0; ch < 3; ch++) {
            float sn = s_q[ch][on - 1] + s_q[ch][on] + s_q[ch][on + 1];
            if (m) {
                float qmean = (sp[ch] + sc[ch] + sn) * inv9;
                float diff = s_q[ch][oc] - qmean;
                acc += diff * diff;
            }
            sp[ch] = sc[ch]; sc[ch] = sn;
        }
        cnt += (unsigned int)m;
    }

    // ---- block reduction ----
    #pragma unroll
    for (int off = 16; off > 0; off >>= 1) {
        acc += __shfl_down_sync(0xffffffffu, acc, off);
        cnt += __shfl_down_sync(0xffffffffu, cnt, off);
    }
    int lane = tid & 31, warp = tid >> 5;
    if (lane == 0) { s_red[warp] = acc; s_redc[warp] = cnt; }
    __syncthreads();
    if (tid == 0) {
        float a = 0.0f; unsigned int cn = 0;
        #pragma unroll
        for (int w = 0; w < 8; w++) { a += s_red[w]; cn += s_redc[w]; }
        atomicAdd(&g_num, (double)a);
        atomicAdd(&g_cnt, cn);
        __threadfence();
        unsigned int t = atomicAdd(&g_ticket, 1u);
        if (t == NBLOCKS - 1) {
            __threadfence();
            double num = g_num;
            unsigned int c2 = g_cnt;
            out[0] = (float)(num / ((double)c2 * 3.0));
            // reset for next graph replay
            g_num = 0.0;
            g_cnt = 0u;
            g_ticket = 0u;
        }
    }
}

extern "C" void kernel_launch(void* const* d_in, const int* in_sizes, int n_in,
                              void* d_out, int out_size) {
    const float* depth = (const float*)d_in[0];
    const float* rgb   = (const float*)d_in[1];
    const int*   mask  = (const int*)d_in[2];
    const float* l     = (const float*)d_in[3];
    const float* Kc    = (const float*)d_in[4];

    dim3 grid(GRID_X, GRID_Y);
    shading_loss_kernel<<<grid, NTHREADS>>>(depth, rgb, mask, l, Kc, (float*)d_out);
}

// round 3
// speedup vs baseline: 2.0568x; 1.3762x over previous
#include <cuda_runtime.h>

#define W_IMG 3840
#define H_IMG 2160
#define TILE_W 32
#define TILE_H 64
#define HALO_W 34            // TILE_W + 2
#define HALO_H 66            // TILE_H + 2
#define DEP_W 35             // HALO_W + 1 (right depth neighbor)
#define DEP_H 67             // HALO_H + 1 (down  depth neighbor)
#define SSTR 36              // padded shared stride
#define NTHREADS 256
#define GRID_X ((W_IMG + TILE_W - 1) / TILE_W)   // 120
#define GRID_Y ((H_IMG + TILE_H - 1) / TILE_H)   // 34
#define NBLOCKS (GRID_X * GRID_Y)

__device__ double g_num;
__device__ unsigned int g_cnt;
__device__ unsigned int g_ticket;

// q = (mask ? B(normal) : 0) - rgb  for one halo pixel.
__device__ __forceinline__ void shade_q(
    float x, float y, float d0, float dl, float du, int m,
    float rg0, float rg1, float rg2,
    const float* __restrict__ Ki, const float* __restrict__ L,
    float& q0, float& q1, float& q2)
{
    float b0 = 0.0f, b1 = 0.0f, b2 = 0.0f;
    if (m) {
        float rx = Ki[0] * x + Ki[1] * y + Ki[2];
        float ry = Ki[3] * x + Ki[4] * y + Ki[5];
        float rz = Ki[6] * x + Ki[7] * y + Ki[8];
        float px = rx * d0, py = ry * d0, pz = rz * d0;
        float ax = (rx + Ki[0]) * dl - px, ay = (ry + Ki[3]) * dl - py, az = (rz + Ki[6]) * dl - pz;
        float bx = (rx + Ki[1]) * du - px, by = (ry + Ki[4]) * du - py, bz = (rz + Ki[7]) * du - pz;
        float nx = ay * bz - az * by;
        float ny = az * bx - ax * bz;
        float nz = ax * by - ay * bx;
        float nn = nx * nx + ny * ny + nz * nz;
        float invn = rsqrtf(fmaxf(nn, 1e-24f));
        nx *= invn; ny *= invn; nz *= invn;
        float nx2 = nx * nx, ny2 = ny * ny, nz2 = nz * nz;
        float Hs1 = ny, Hs2 = nz, Hs3 = nx;
        float Hs4 = nx * ny, Hs5 = ny * nz;
        float Hs6 = 2.0f * nz2 - nx2 - ny2;
        float Hs7 = nz * nx, Hs8 = nx2 - ny2;
        b0 = L[0] + Hs1*L[3]  + Hs2*L[6]  + Hs3*L[9]  + Hs4*L[12] + Hs5*L[15] + Hs6*L[18] + Hs7*L[21] + Hs8*L[24];
        b1 = L[1] + Hs1*L[4]  + Hs2*L[7]  + Hs3*L[10] + Hs4*L[13] + Hs5*L[16] + Hs6*L[19] + Hs7*L[22] + Hs8*L[25];
        b2 = L[2] + Hs1*L[5]  + Hs2*L[8]  + Hs3*L[11] + Hs4*L[14] + Hs5*L[17] + Hs6*L[20] + Hs7*L[23] + Hs8*L[26];
    }
    q0 = b0 - rg0;
    q1 = b1 - rg1;
    q2 = b2 - rg2;
}

__launch_bounds__(NTHREADS, 4)
__global__ void shading_loss_kernel(const float* __restrict__ depth,
                                    const float* __restrict__ rgb,
                                    const int*   __restrict__ mask,
                                    const float* __restrict__ l,
                                    const float* __restrict__ Kc,
                                    float* __restrict__ out)
{
    __shared__ float s_depth[DEP_H * SSTR];
    __shared__ float s_q[3][HALO_H * SSTR];
    __shared__ unsigned char s_mask[HALO_H * SSTR];
    __shared__ float s_Ki[9];
    __shared__ float s_l[27];
    __shared__ float s_red[8];
    __shared__ unsigned int s_redc[8];

    const int tid  = threadIdx.x;
    const int col0 = blockIdx.x * TILE_W;
    const int row0 = blockIdx.y * TILE_H;

    const bool interior = (col0 >= 1) && (row0 >= 1) &&
                          (col0 + HALO_W <= W_IMG) && (row0 + HALO_H <= H_IMG);

    if (tid == 0) {
        float a = Kc[0], b = Kc[1], c = Kc[2];
        float d = Kc[3], e = Kc[4], f = Kc[5];
        float g = Kc[6], h = Kc[7], i = Kc[8];
        float A =  (e*i - f*h), B = -(d*i - f*g), C =  (d*h - e*g);
        float inv = 1.0f / (a*A + b*B + c*C);
        s_Ki[0] = A * inv;            s_Ki[1] = -(b*i - c*h) * inv;  s_Ki[2] =  (b*f - c*e) * inv;
        s_Ki[3] = B * inv;            s_Ki[4] =  (a*i - c*g) * inv;  s_Ki[5] = -(a*f - c*d) * inv;
        s_Ki[6] = C * inv;            s_Ki[7] = -(a*h - b*g) * inv;  s_Ki[8] =  (a*e - b*d) * inv;
    }
    if (tid < 27) s_l[tid] = l[tid];

    // ---- stage 1: depth halo (32-bit offsets) ----
    const int base0 = (row0 - 1) * W_IMG + (col0 - 1);
    if (interior) {
        for (unsigned idx = tid; idx < DEP_H * DEP_W; idx += NTHREADS) {
            unsigned r = idx / DEP_W, c = idx - r * DEP_W;
            s_depth[r * SSTR + c] = depth[base0 + (int)r * W_IMG + (int)c];
        }
    } else {
        for (unsigned idx = tid; idx < DEP_H * DEP_W; idx += NTHREADS) {
            unsigned r = idx / DEP_W, c = idx - r * DEP_W;
            int gr = row0 - 1 + (int)r, gc = col0 - 1 + (int)c;
            float v = 0.0f;
            if (gr >= 0 && gr < H_IMG && gc >= 0 && gc < W_IMG)
                v = depth[gr * W_IMG + gc];
            s_depth[r * SSTR + c] = v;
        }
    }
    __syncthreads();

    // ---- stage 2: shade -> q over halo (rgb + mask direct from gmem) ----
    if (interior) {
        for (unsigned idx = tid; idx < HALO_H * HALO_W; idx += NTHREADS) {
            unsigned r = idx / HALO_W, c = idx - r * HALO_W;
            int goff = base0 + (int)r * W_IMG + (int)c;
            int m = mask[goff] > 0;
            int ro = goff * 3;
            float rg0 = rgb[ro], rg1 = rgb[ro + 1], rg2 = rgb[ro + 2];
            float d0 = s_depth[r * SSTR + c];
            float dl = s_depth[r * SSTR + c + 1];
            float du = s_depth[(r + 1) * SSTR + c];
            float q0, q1, q2;
            shade_q((float)(col0 - 1 + (int)c), (float)(row0 - 1 + (int)r),
                    d0, dl, du, m, rg0, rg1, rg2, s_Ki, s_l, q0, q1, q2);
            s_q[0][r * SSTR + c] = q0;
            s_q[1][r * SSTR + c] = q1;
            s_q[2][r * SSTR + c] = q2;
            s_mask[r * SSTR + c] = (unsigned char)m;
        }
    } else {
        for (unsigned idx = tid; idx < HALO_H * HALO_W; idx += NTHREADS) {
            unsigned r = idx / HALO_W, c = idx - r * HALO_W;
            int gr = row0 - 1 + (int)r, gc = col0 - 1 + (int)c;
            bool inimg = (gr >= 0 && gr < H_IMG && gc >= 0 && gc < W_IMG);
            int m = 0;
            float rg0 = 0.0f, rg1 = 0.0f, rg2 = 0.0f;
            if (inimg) {
                int goff = gr * W_IMG + gc;
                m = mask[goff] > 0;
                int ro = goff * 3;
                rg0 = rgb[ro]; rg1 = rgb[ro + 1]; rg2 = rgb[ro + 2];
            }
            float d0 = s_depth[r * SSTR + c];
            float dl = s_depth[r * SSTR + c + 1];
            float du = s_depth[(r + 1) * SSTR + c];
            float q0, q1, q2;
            shade_q((float)gc, (float)gr, d0, dl, du, m, rg0, rg1, rg2,
                    s_Ki, s_l, q0, q1, q2);
            s_q[0][r * SSTR + c] = q0;
            s_q[1][r * SSTR + c] = q1;
            s_q[2][r * SSTR + c] = q2;
            s_mask[r * SSTR + c] = (unsigned char)m;
        }
    }
    __syncthreads();

    // ---- stage 3: 3x3 avgpool of q (vertical sliding window) + masked MSE ----
    const int c  = tid & 31;
    const int rg = tid >> 5;           // 8 output rows per thread
    const int hc  = c + 1;
    const int hr0 = rg * 8 + 1;
    const float inv9 = 1.0f / 9.0f;

    float acc = 0.0f;
    unsigned int cnt = 0;

    float sp[3], sc[3];
    #pragma unroll
    for (int ch = 0; ch < 3; ch++) {
        int o = (hr0 - 1) * SSTR + hc;
        sp[ch] = s_q[ch][o - 1] + s_q[ch][o] + s_q[ch][o + 1];
        o += SSTR;
        sc[ch] = s_q[ch][o - 1] + s_q[ch][o] + s_q[ch][o + 1];
    }
    #pragma unroll
    for (int k = 0; k < 8; k++) {
        int hr = hr0 + k;
        int on = (hr + 1) * SSTR + hc;
        int oc = hr * SSTR + hc;
        unsigned char m = s_mask[oc];
        #pragma unroll
        for (int ch = 0; ch < 3; ch++) {
            float sn = s_q[ch][on - 1] + s_q[ch][on] + s_q[ch][on + 1];
            if (m) {
                float qmean = (sp[ch] + sc[ch] + sn) * inv9;
                float diff = s_q[ch][oc] - qmean;
                acc += diff * diff;
            }
            sp[ch] = sc[ch]; sc[ch] = sn;
        }
        cnt += (unsigned int)m;
    }

    // ---- block reduction ----
    #pragma unroll
    for (int off = 16; off > 0; off >>= 1) {
        acc += __shfl_down_sync(0xffffffffu, acc, off);
        cnt += __shfl_down_sync(0xffffffffu, cnt, off);
    }
    int lane = tid & 31, warp = tid >> 5;
    if (lane == 0) { s_red[warp] = acc; s_redc[warp] = cnt; }
    __syncthreads();
    if (tid == 0) {
        float a = 0.0f; unsigned int cn = 0;
        #pragma unroll
        for (int w = 0; w < 8; w++) { a += s_red[w]; cn += s_redc[w]; }
        atomicAdd(&g_num, (double)a);
        atomicAdd(&g_cnt, cn);
        __threadfence();
        unsigned int t = atomicAdd(&g_ticket, 1u);
        if (t == NBLOCKS - 1) {
            __threadfence();
            double num = g_num;
            unsigned int c2 = g_cnt;
            out[0] = (float)(num / ((double)c2 * 3.0));
            g_num = 0.0;
            g_cnt = 0u;
            g_ticket = 0u;
        }
    }
}

extern "C" void kernel_launch(void* const* d_in, const int* in_sizes, int n_in,
                              void* d_out, int out_size) {
    const float* depth = (const float*)d_in[0];
    const float* rgb   = (const float*)d_in[1];
    const int*   mask  = (const int*)d_in[2];
    const float* l     = (const float*)d_in[3];
    const float* Kc    = (const float*)d_in[4];

    dim3 grid(GRID_X, GRID_Y);
    shading_loss_kernel<<<grid, NTHREADS>>>(depth, rgb, mask, l, Kc, (float*)d_out);
}

// round 4
// speedup vs baseline: 2.3566x; 1.1458x over previous
#include <cuda_runtime.h>

#define W_IMG 3840
#define H_IMG 2160
#define TILE_W 30            // output columns per warp (lanes 1..30)
#define STRIP_H 40           // output rows per warp
#define NW_X 128             // 3840 / 30
#define NW_Y 54              // 2160 / 40
#define WPB 8                // warps per block
#define NTHREADS 256
#define NBLOCKS (NW_X * NW_Y / WPB)   // 864

__device__ double g_num;
__device__ unsigned int g_cnt;
__device__ unsigned int g_ticket;

__launch_bounds__(NTHREADS, 4)
__global__ void shading_loss_kernel(const float* __restrict__ depth,
                                    const float* __restrict__ rgb,
                                    const int*   __restrict__ mask,
                                    const float* __restrict__ l,
                                    const float* __restrict__ Kc,
                                    float* __restrict__ out)
{
    const int tid  = threadIdx.x;
    const int lane = tid & 31;
    const int w    = tid >> 5;
    const int wid  = blockIdx.x * WPB + w;
    const int tx   = wid % NW_X;
    const int ty   = wid / NW_X;
    const int c0   = tx * TILE_W;
    const int r0   = ty * STRIP_H;
    const int col  = c0 - 1 + lane;          // lane's column (includes halo)
    const bool colin  = (col >= 0) && (col < W_IMG);
    const bool colrin = (col + 1 < W_IMG);   // col+1 >= 0 always

    // camera inverse (adjugate) — uniform, computed per thread (cheap, once)
    float a = Kc[0], b = Kc[1], cc = Kc[2];
    float d = Kc[3], e = Kc[4], f  = Kc[5];
    float g = Kc[6], h = Kc[7], i  = Kc[8];
    float A =  (e*i - f*h), B = -(d*i - f*g), C =  (d*h - e*g);
    float inv = 1.0f / (a*A + b*B + cc*C);
    float K0 = A*inv,  K1 = -(b*i - cc*h)*inv,  K2 =  (b*f - cc*e)*inv;
    float K3 = B*inv,  K4 =  (a*i - cc*g)*inv,  K5 = -(a*f - cc*d)*inv;
    float K6 = C*inv,  K7 = -(a*h - b*g)*inv,   K8 =  (a*e - b*d)*inv;

    // per-lane ray components at y=0: ray(y) = (ax_+K1*y, ay_+K4*y, az_+K7*y)
    const float x  = (float)col;
    const float ax_ = K0 * x + K2;
    const float ay_ = K3 * x + K5;
    const float az_ = K6 * x + K8;

    int off = (r0 - 1) * W_IMG + col;
    float dA = 0.0f;                          // depth(row r, col)
    if (colin && r0 >= 1) dA = depth[off];

    // vertical pipeline registers
    float hsA0=0.f,hsA1=0.f,hsA2=0.f;         // hsum(row r-2)
    float hsB0=0.f,hsB1=0.f,hsB2=0.f;         // hsum(row r-1)
    float qC0=0.f,qC1=0.f,qC2=0.f;            // q(row r-1)
    int   mC = 0;                             // mask(row r-1)

    float acc = 0.0f;
    unsigned int cnt = 0;
    const bool emitlane = (lane >= 1) && (lane <= 30);
    const float inv9 = 1.0f / 9.0f;

    #pragma unroll 1
    for (int r = r0 - 1; r <= r0 + STRIP_H; ++r) {
        const bool rin  = ((unsigned)r < (unsigned)H_IMG);
        const bool rnin = ((unsigned)(r + 1) < (unsigned)H_IMG);

        float dB = (rnin && colin)  ? depth[off + W_IMG] : 0.0f;  // down neighbor
        float dR = (rin  && colrin) ? depth[off + 1]     : 0.0f;  // right neighbor
        int   m  = 0;
        float rg0 = 0.0f, rg1 = 0.0f, rg2 = 0.0f;
        if (rin && colin) {
            m = mask[off] > 0;
            int ro3 = off * 3;
            rg0 = rgb[ro3]; rg1 = rgb[ro3 + 1]; rg2 = rgb[ro3 + 2];
        }

        // shade -> q = (m ? B(normal) : 0) - rgb
        float b0 = 0.0f, b1 = 0.0f, b2 = 0.0f;
        if (m) {
            float y  = (float)r;
            float rx = ax_ + K1 * y;
            float ry = ay_ + K4 * y;
            float rz = az_ + K7 * y;
            float px = rx * dA, py = ry * dA, pz = rz * dA;
            float axv = (rx + K0) * dR - px, ayv = (ry + K3) * dR - py, azv = (rz + K6) * dR - pz;
            float bxv = (rx + K1) * dB - px, byv = (ry + K4) * dB - py, bzv = (rz + K7) * dB - pz;
            float nx = ayv * bzv - azv * byv;
            float ny = azv * bxv - axv * bzv;
            float nz = axv * byv - ayv * bxv;
            float nn = nx*nx + ny*ny + nz*nz;
            float invn = rsqrtf(fmaxf(nn, 1e-24f));
            nx *= invn; ny *= invn; nz *= invn;
            float nx2 = nx*nx, ny2 = ny*ny, nz2 = nz*nz;
            float H1 = ny, H2 = nz, H3 = nx;
            float H4 = nx*ny, H5 = ny*nz;
            float H6 = 2.0f*nz2 - nx2 - ny2;
            float H7 = nz*nx, H8 = nx2 - ny2;
            b0 = l[0] + H1*l[3]  + H2*l[6]  + H3*l[9]  + H4*l[12] + H5*l[15] + H6*l[18] + H7*l[21] + H8*l[24];
            b1 = l[1] + H1*l[4]  + H2*l[7]  + H3*l[10] + H4*l[13] + H5*l[16] + H6*l[19] + H7*l[22] + H8*l[25];
            b2 = l[2] + H1*l[5]  + H2*l[8]  + H3*l[11] + H4*l[14] + H5*l[17] + H6*l[20] + H7*l[23] + H8*l[26];
        }
        float q0 = b0 - rg0, q1 = b1 - rg1, q2 = b2 - rg2;

        // horizontal 3-sum via shuffles (valid at lanes 1..30)
        float ql0 = __shfl_up_sync(0xffffffffu, q0, 1), qr0 = __shfl_down_sync(0xffffffffu, q0, 1);
        float ql1 = __shfl_up_sync(0xffffffffu, q1, 1), qr1 = __shfl_down_sync(0xffffffffu, q1, 1);
        float ql2 = __shfl_up_sync(0xffffffffu, q2, 1), qr2 = __shfl_down_sync(0xffffffffu, q2, 1);
        float hs0 = ql0 + q0 + qr0;
        float hs1 = ql1 + q1 + qr1;
        float hs2 = ql2 + q2 + qr2;

        // emit output row r-1 once we hold hsum(r-2), hsum(r-1), hsum(r)
        if (r > r0) {
            if (emitlane && mC) {
                float d0 = qC0 - (hsA0 + hsB0 + hs0) * inv9;
                float d1 = qC1 - (hsA1 + hsB1 + hs1) * inv9;
                float d2 = qC2 - (hsA2 + hsB2 + hs2) * inv9;
                acc += d0*d0 + d1*d1 + d2*d2;
                cnt += 1u;
            }
        }

        // shift pipeline
        hsA0 = hsB0; hsA1 = hsB1; hsA2 = hsB2;
        hsB0 = hs0;  hsB1 = hs1;  hsB2 = hs2;
        qC0 = q0; qC1 = q1; qC2 = q2; mC = m;
        dA = dB;
        off += W_IMG;
    }

    // ---- reduction: warp -> block -> global ----
    #pragma unroll
    for (int o = 16; o > 0; o >>= 1) {
        acc += __shfl_down_sync(0xffffffffu, acc, o);
        cnt += __shfl_down_sync(0xffffffffu, cnt, o);
    }
    __shared__ float s_red[WPB];
    __shared__ unsigned int s_redc[WPB];
    if (lane == 0) { s_red[w] = acc; s_redc[w] = cnt; }
    __syncthreads();
    if (tid == 0) {
        float aa = 0.0f; unsigned int cn = 0;
        #pragma unroll
        for (int k = 0; k < WPB; k++) { aa += s_red[k]; cn += s_redc[k]; }
        atomicAdd(&g_num, (double)aa);
        atomicAdd(&g_cnt, cn);
        __threadfence();
        unsigned int t = atomicAdd(&g_ticket, 1u);
        if (t == NBLOCKS - 1) {
            __threadfence();
            double num = g_num;
            unsigned int c2 = g_cnt;
            out[0] = (float)(num / ((double)c2 * 3.0));
            g_num = 0.0;
            g_cnt = 0u;
            g_ticket = 0u;
        }
    }
}

extern "C" void kernel_launch(void* const* d_in, const int* in_sizes, int n_in,
                              void* d_out, int out_size) {
    const float* depth = (const float*)d_in[0];
    const float* rgb   = (const float*)d_in[1];
    const int*   mask  = (const int*)d_in[2];
    const float* l     = (const float*)d_in[3];
    const float* Kc    = (const float*)d_in[4];

    shading_loss_kernel<<<NBLOCKS, NTHREADS>>>(depth, rgb, mask, l, Kc, (float*)d_out);
}